// round 8
// baseline (speedup 1.0000x reference)
#include <cuda_runtime.h>
#include <cstdint>

#define BB 512
#define TT 128
#define CC 384
#define HD 64
#define NT 512
#define ATT_SCALE 0.4082482904638631f  // 6^-0.5

// ---- smem layout (floats). Region0 aliased: phase1 operands vs P + partials.
//  sXhi [128][36] @0      (4608)
//  sXlo [128][36] @4608   (4608)
//  sWhi [32][200] @9216   (6400)
//  sWlo [32][200] @15616  (6400)   end 22016
//  sS   [128][132] @0     (16896)  (aliased)
//  pmx  [128][2]   @16896 (256)
//  psum [128][2]   @17152 (256)
//  sQ   [128][68] @22016  (8704)
//  sK   [128][68] @30720  (8704)
//  sV   [128][72] @39424  (9216)   end 48640 floats = 194560 bytes
#define OXH 0
#define OXL 4608
#define OWH 9216
#define OWL 15616
#define OS  0
#define OPM 16896
#define OPS 17152
#define OQ  22016
#define OK  30720
#define OV  39424
#define SMEM_FLOATS 48640
#define SMEM_BYTES (SMEM_FLOATS * 4)

__device__ __forceinline__ uint32_t f2tf32(float x) {
    uint32_t r;
    asm("cvt.rna.tf32.f32 %0, %1;" : "=r"(r) : "f"(x));
    return r;
}
__device__ __forceinline__ void split_tf32(float x, uint32_t& hi, uint32_t& lo) {
    hi = f2tf32(x);
    lo = f2tf32(x - __uint_as_float(hi));
}
__device__ __forceinline__ void mma_tf32(float* d, const uint32_t* a, uint32_t b0, uint32_t b1) {
    asm volatile(
        "mma.sync.aligned.m16n8k8.row.col.f32.tf32.tf32.f32 "
        "{%0,%1,%2,%3}, {%4,%5,%6,%7}, {%8,%9}, {%0,%1,%2,%3};"
        : "+f"(d[0]), "+f"(d[1]), "+f"(d[2]), "+f"(d[3])
        : "r"(a[0]), "r"(a[1]), "r"(a[2]), "r"(a[3]), "r"(b0), "r"(b1));
}

__global__ __launch_bounds__(NT, 1)
void head_mma_kernel(const float* __restrict__ x,
                     const float* __restrict__ Wq,
                     const float* __restrict__ Wk,
                     const float* __restrict__ Wv,
                     float* __restrict__ out) {
    extern __shared__ float sm[];
    const int tid  = threadIdx.x;
    const int lane = tid & 31;
    const int wid  = tid >> 5;
    const int g    = lane >> 2;   // 0..7
    const int q4   = lane & 3;    // 0..3
    const int b    = blockIdx.x;
    const float* xb = x + (size_t)b * TT * CC;
    const float* Ws[3] = {Wq, Wk, Wv};

    // ================= Phase 1: QKV projection =================
    // 16 warps: wm = wid&7 -> 16-row stripe; wn = wid>>3 -> 96-col half of 192
    const int wm = wid & 7;
    const int wn = wid >> 3;

    float accp[12][4];
    #pragma unroll
    for (int ni = 0; ni < 12; ni++)
        #pragma unroll
        for (int j = 0; j < 4; j++) accp[ni][j] = 0.f;

    for (int ch = 0; ch < 12; ch++) {
        if (ch) __syncthreads();
        // X chunk [128][32] -> hi/lo (1024 float4, 2/thread)
        #pragma unroll
        for (int rep = 0; rep < 2; rep++) {
            int lin = rep * NT + tid;
            int row = lin >> 3;
            int c4  = (lin & 7) << 2;
            float4 v = *reinterpret_cast<const float4*>(xb + row * CC + ch * 32 + c4);
            float4 h, l;
            uint32_t uh, ul;
            split_tf32(v.x, uh, ul); h.x = __uint_as_float(uh); l.x = __uint_as_float(ul);
            split_tf32(v.y, uh, ul); h.y = __uint_as_float(uh); l.y = __uint_as_float(ul);
            split_tf32(v.z, uh, ul); h.z = __uint_as_float(uh); l.z = __uint_as_float(ul);
            split_tf32(v.w, uh, ul); h.w = __uint_as_float(uh); l.w = __uint_as_float(ul);
            int off = row * 36 + c4;
            *reinterpret_cast<float4*>(sm + OXH + off) = h;
            *reinterpret_cast<float4*>(sm + OXL + off) = l;
        }
        // W chunk [32][192] -> hi/lo (1536 float4, 3/thread)
        #pragma unroll
        for (int rep = 0; rep < 3; rep++) {
            int lin  = rep * NT + tid;
            int wsel = lin >> 9;
            int rem  = lin & 511;
            int row  = rem >> 4;
            int c4   = (rem & 15) << 2;
            float4 v = *reinterpret_cast<const float4*>(Ws[wsel] + (ch * 32 + row) * HD + c4);
            float4 h, l;
            uint32_t uh, ul;
            split_tf32(v.x, uh, ul); h.x = __uint_as_float(uh); l.x = __uint_as_float(ul);
            split_tf32(v.y, uh, ul); h.y = __uint_as_float(uh); l.y = __uint_as_float(ul);
            split_tf32(v.z, uh, ul); h.z = __uint_as_float(uh); l.z = __uint_as_float(ul);
            split_tf32(v.w, uh, ul); h.w = __uint_as_float(uh); l.w = __uint_as_float(ul);
            int off = row * 200 + wsel * HD + c4;
            *reinterpret_cast<float4*>(sm + OWH + off) = h;
            *reinterpret_cast<float4*>(sm + OWL + off) = l;
        }
        __syncthreads();

        #pragma unroll
        for (int k8 = 0; k8 < 4; k8++) {
            int kk = k8 * 8 + q4;
            int r = wm * 16 + g;
            uint32_t ahi[4], alo[4];
            ahi[0] = __float_as_uint(sm[OXH + r * 36 + kk]);
            ahi[1] = __float_as_uint(sm[OXH + (r + 8) * 36 + kk]);
            ahi[2] = __float_as_uint(sm[OXH + r * 36 + kk + 4]);
            ahi[3] = __float_as_uint(sm[OXH + (r + 8) * 36 + kk + 4]);
            alo[0] = __float_as_uint(sm[OXL + r * 36 + kk]);
            alo[1] = __float_as_uint(sm[OXL + (r + 8) * 36 + kk]);
            alo[2] = __float_as_uint(sm[OXL + r * 36 + kk + 4]);
            alo[3] = __float_as_uint(sm[OXL + (r + 8) * 36 + kk + 4]);
            #pragma unroll
            for (int ni = 0; ni < 12; ni++) {
                int nb   = wn * 96 + ni * 8;
                int boff = kk * 200 + nb + g;
                uint32_t bh0 = __float_as_uint(sm[OWH + boff]);
                uint32_t bh1 = __float_as_uint(sm[OWH + boff + 800]);
                mma_tf32(accp[ni], ahi, bh0, bh1);
                if (nb < 128) {  // Q,K columns: 3xTF32 compensation
                    uint32_t bl0 = __float_as_uint(sm[OWL + boff]);
                    uint32_t bl1 = __float_as_uint(sm[OWL + boff + 800]);
                    mma_tf32(accp[ni], ahi, bl0, bl1);
                    mma_tf32(accp[ni], alo, bh0, bh1);
                }
            }
        }
    }

    // store Q,K (fp32) and V (tf32-rounded) to smem
    #pragma unroll
    for (int ni = 0; ni < 12; ni++) {
        int nc = wn * 96 + ni * 8 + 2 * q4;
        #pragma unroll
        for (int half = 0; half < 2; half++) {
            int r = wm * 16 + g + half * 8;
            float v0 = accp[ni][half * 2];
            float v1 = accp[ni][half * 2 + 1];
            if (nc < 64) {
                *reinterpret_cast<float2*>(sm + OQ + r * 68 + nc) = make_float2(v0, v1);
            } else if (nc < 128) {
                *reinterpret_cast<float2*>(sm + OK + r * 68 + nc - 64) = make_float2(v0, v1);
            } else {
                *reinterpret_cast<float2*>(sm + OV + r * 72 + nc - 128) =
                    make_float2(__uint_as_float(f2tf32(v0)), __uint_as_float(f2tf32(v1)));
            }
        }
    }
    __syncthreads();  // QKV visible; phase-1 operand region reusable as sS/partials

    // ================= Phase 2: S = Q K^T (3xTF32) =================
    // warp (s,h): rows s*16..s*16+15, cols h*64..h*64+63
    const int ss = wid & 7;
    const int hh = wid >> 3;
    const int m0 = ss * 16;
    const int n0 = hh * 64;
    const int r0 = m0 + g;
    const int r1 = r0 + 8;
    const bool skip = (hh == 1) && (ss < 4);   // fully-masked block

    float acc2[8][4];
    float mx0 = -1e30f, mx1 = -1e30f, sum0 = 0.f, sum1 = 0.f;

    if (!skip) {
        #pragma unroll
        for (int ni = 0; ni < 8; ni++)
            #pragma unroll
            for (int j = 0; j < 4; j++) acc2[ni][j] = 0.f;

        #pragma unroll
        for (int k8 = 0; k8 < 8; k8++) {
            int kk = k8 * 8 + q4;
            uint32_t ah[4], al[4];
            split_tf32(sm[OQ + r0 * 68 + kk],     ah[0], al[0]);
            split_tf32(sm[OQ + r1 * 68 + kk],     ah[1], al[1]);
            split_tf32(sm[OQ + r0 * 68 + kk + 4], ah[2], al[2]);
            split_tf32(sm[OQ + r1 * 68 + kk + 4], ah[3], al[3]);
            #pragma unroll
            for (int ni = 0; ni < 8; ni++) {
                int koff = (n0 + ni * 8 + g) * 68 + kk;
                uint32_t bh0, bl0, bh1, bl1;
                split_tf32(sm[OK + koff],     bh0, bl0);
                split_tf32(sm[OK + koff + 4], bh1, bl1);
                mma_tf32(acc2[ni], ah, bh0, bh1);
                mma_tf32(acc2[ni], ah, bl0, bl1);
                mma_tf32(acc2[ni], al, bh0, bh1);
            }
        }
        // mask + scale + local max over this 64-col half
        #pragma unroll
        for (int ni = 0; ni < 8; ni++)
            #pragma unroll
            for (int j = 0; j < 2; j++) {
                int c = n0 + ni * 8 + 2 * q4 + j;
                float s0 = acc2[ni][j] * ATT_SCALE;
                float s1 = acc2[ni][2 + j] * ATT_SCALE;
                acc2[ni][j]     = (c <= r0) ? s0 : -1e30f;
                acc2[ni][2 + j] = (c <= r1) ? s1 : -1e30f;
                mx0 = fmaxf(mx0, acc2[ni][j]);
                mx1 = fmaxf(mx1, acc2[ni][2 + j]);
            }
        mx0 = fmaxf(mx0, __shfl_xor_sync(0xffffffffu, mx0, 1));
        mx0 = fmaxf(mx0, __shfl_xor_sync(0xffffffffu, mx0, 2));
        mx1 = fmaxf(mx1, __shfl_xor_sync(0xffffffffu, mx1, 1));
        mx1 = fmaxf(mx1, __shfl_xor_sync(0xffffffffu, mx1, 2));
        // local exp + partial sums (masked entries -> exp(-1e30 - mx) == 0)
        #pragma unroll
        for (int ni = 0; ni < 8; ni++)
            #pragma unroll
            for (int j = 0; j < 2; j++) {
                float e0 = __expf(acc2[ni][j] - mx0);
                float e1 = __expf(acc2[ni][2 + j] - mx1);
                acc2[ni][j] = e0; acc2[ni][2 + j] = e1;
                sum0 += e0; sum1 += e1;
            }
        sum0 += __shfl_xor_sync(0xffffffffu, sum0, 1);
        sum0 += __shfl_xor_sync(0xffffffffu, sum0, 2);
        sum1 += __shfl_xor_sync(0xffffffffu, sum1, 1);
        sum1 += __shfl_xor_sync(0xffffffffu, sum1, 2);
    }
    // publish partials (one lane per row)
    if (q4 == 0) {
        sm[OPM + r0 * 2 + hh] = mx0;
        sm[OPM + r1 * 2 + hh] = mx1;
        sm[OPS + r0 * 2 + hh] = sum0;
        sm[OPS + r1 * 2 + hh] = sum1;
    }
    __syncthreads();

    // combine halves, normalize, store P (tf32-rounded) to sS
    if (!skip) {
        float pa0 = sm[OPM + r0 * 2], pb0 = sm[OPM + r0 * 2 + 1];
        float pa1 = sm[OPM + r1 * 2], pb1 = sm[OPM + r1 * 2 + 1];
        float gmx0 = fmaxf(pa0, pb0), gmx1 = fmaxf(pa1, pb1);
        float gs0 = sm[OPS + r0 * 2] * __expf(pa0 - gmx0) + sm[OPS + r0 * 2 + 1] * __expf(pb0 - gmx0);
        float gs1 = sm[OPS + r1 * 2] * __expf(pa1 - gmx1) + sm[OPS + r1 * 2 + 1] * __expf(pb1 - gmx1);
        float fac0 = __expf(mx0 - gmx0) / gs0;
        float fac1 = __expf(mx1 - gmx1) / gs1;
        #pragma unroll
        for (int ni = 0; ni < 8; ni++) {
            int c = n0 + ni * 8 + 2 * q4;
            *reinterpret_cast<float2*>(sm + OS + r0 * 132 + c) =
                make_float2(__uint_as_float(f2tf32(acc2[ni][0] * fac0)),
                            __uint_as_float(f2tf32(acc2[ni][1] * fac0)));
            *reinterpret_cast<float2*>(sm + OS + r1 * 132 + c) =
                make_float2(__uint_as_float(f2tf32(acc2[ni][2] * fac1)),
                            __uint_as_float(f2tf32(acc2[ni][3] * fac1)));
        }
    } else {
        #pragma unroll
        for (int ni = 0; ni < 8; ni++) {
            int c = n0 + ni * 8 + 2 * q4;
            *reinterpret_cast<float2*>(sm + OS + r0 * 132 + c) = make_float2(0.f, 0.f);
            *reinterpret_cast<float2*>(sm + OS + r1 * 132 + c) = make_float2(0.f, 0.f);
        }
    }
    __syncthreads();

    // ================= Phase 4: O = P V (single-pass tf32) =================
    // warp (s,h): O rows m0..m0+15, cols h*32..h*32+31; K truncated causally.
    const int c0 = hh * 32;
    float acc4[4][4];
    #pragma unroll
    for (int ni = 0; ni < 4; ni++)
        #pragma unroll
        for (int j = 0; j < 4; j++) acc4[ni][j] = 0.f;

    const int k8max = 2 * ss + 2;   // P cols > 16s+15 are exact zeros
    for (int k8 = 0; k8 < k8max; k8++) {
        int kk = k8 * 8 + q4;
        uint32_t ap[4];
        ap[0] = __float_as_uint(sm[OS + r0 * 132 + kk]);
        ap[1] = __float_as_uint(sm[OS + r1 * 132 + kk]);
        ap[2] = __float_as_uint(sm[OS + r0 * 132 + kk + 4]);
        ap[3] = __float_as_uint(sm[OS + r1 * 132 + kk + 4]);
        #pragma unroll
        for (int ni = 0; ni < 4; ni++) {
            int voff = kk * 72 + c0 + ni * 8 + g;
            uint32_t b0 = __float_as_uint(sm[OV + voff]);
            uint32_t b1 = __float_as_uint(sm[OV + voff + 288]);
            mma_tf32(acc4[ni], ap, b0, b1);
        }
    }

    // ================= epilogue =================
    {
        float* ob = out + (size_t)b * TT * HD;
        #pragma unroll
        for (int ni = 0; ni < 4; ni++) {
            int c = c0 + ni * 8 + 2 * q4;
            *reinterpret_cast<float2*>(ob + r0 * HD + c) = make_float2(acc4[ni][0], acc4[ni][1]);
            *reinterpret_cast<float2*>(ob + r1 * HD + c) = make_float2(acc4[ni][2], acc4[ni][3]);
        }
    }
}

extern "C" void kernel_launch(void* const* d_in, const int* in_sizes, int n_in,
                              void* d_out, int out_size) {
    const float* x  = (const float*)d_in[0];
    const float* Wq = (const float*)d_in[1];
    const float* Wk = (const float*)d_in[2];
    const float* Wv = (const float*)d_in[3];
    float* out = (float*)d_out;

    cudaFuncSetAttribute(head_mma_kernel,
                         cudaFuncAttributeMaxDynamicSharedMemorySize, SMEM_BYTES);
    head_mma_kernel<<<BB, NT, SMEM_BYTES>>>(x, Wq, Wk, Wv, out);
}